// round 2
// baseline (speedup 1.0000x reference)
#include <cuda_runtime.h>
#include <math.h>

// EmbeddingToExpression: per-region MLP 16 -> 5 (exact-erf GELU) -> 1
//   R=1024, C=8192, DIN=16, E=5, NREG=2048. out[c,r], f32.
//
// HBM-bound (512 MiB stream + 32 MiB transposed write; floor ~68us).
// R1 was latency-bound at occ 24% (128 regs: 80-float weight array).
// R2: e-split across lane pairs -> 48 weight regs, __launch_bounds__(256,3)
// for 24 warps/SM. Lane pair (2i,2i+1) co-owns a cell:
//   even lane: e in {0,1,2}; odd lane: e in {3,4,4-pad(wf=0)}.
// Uniform instruction stream (no divergence); shfl_xor(1) combines partials.

#define RR    1024
#define CC    8192
#define DIN   16
#define EE    5
#define CPB   256   // cells per block
#define RPB   8     // regions per block (one warp each)

__global__ __launch_bounds__(256, 3)
void e2e_kernel(const float* __restrict__ emb,
                const void*  __restrict__ oi,     // int32 or int64, detected
                const float* __restrict__ W1,     // [NREG, DIN, E]
                const float* __restrict__ b1,     // [NREG, E]
                const float* __restrict__ Wf,     // [NREG, E, 1]
                float* __restrict__ out)          // [C, R]
{
    __shared__ float s_out[RPB * CPB];
    __shared__ int   s_is64;

    // Detect regions_oi width (values < 2048: int64 => odd words all zero).
    if (threadIdx.x == 0) {
        const int* w = (const int*)oi;
        int all0 = 1;
        #pragma unroll
        for (int k = 0; k < 32; k++) all0 &= (w[2 * k + 1] == 0);
        s_is64 = all0;
    }
    __syncthreads();

    const int warp = threadIdx.x >> 5;
    const int lane = threadIdx.x & 31;
    const int par  = lane & 1;                  // 0: e{0,1,2}, 1: e{3,4,pad}
    const int r    = blockIdx.y * RPB + warp;
    const int c0   = blockIdx.x * CPB;

    int reg;
    if (s_is64) reg = (int)((const long long*)oi)[r];
    else        reg = ((const int*)oi)[r];

    // ---- this lane's 3-wide e-slice of weights (48 regs) ----
    const int eBase = par ? 3 : 0;
    float w[DIN * 3];                           // w[i*3 + j] = W1[reg][i][eBase+j]
    {
        const float* wp = W1 + (size_t)reg * (DIN * EE) + eBase;
        #pragma unroll
        for (int i = 0; i < DIN; i++) {
            w[i * 3 + 0] = wp[i * EE + 0];
            w[i * 3 + 1] = wp[i * EE + 1];
            w[i * 3 + 2] = wp[i * EE + (par ? 1 : 2)];   // pad dups e=4
        }
    }
    float bb0 = b1[reg * EE + eBase + 0];
    float bb1 = b1[reg * EE + eBase + 1];
    float bb2 = b1[reg * EE + eBase + (par ? 1 : 2)];
    float wf0 = Wf[reg * EE + eBase + 0];
    float wf1 = Wf[reg * EE + eBase + 1];
    float wf2 = par ? 0.0f : Wf[reg * EE + 2];           // pad slot contributes 0

    // ---- stream cells: pair (2i,2i+1) owns cell i of each 16-cell pass ----
    const float4* ep = (const float4*)(emb + ((size_t)r * CC + c0) * DIN);

    #pragma unroll 4
    for (int p = 0; p < CPB / 16; p++) {
        const int cl = p * 16 + (lane >> 1);
        const float4* cp = ep + cl * 4;

        float h0 = bb0, h1 = bb1, h2 = bb2;
        #pragma unroll
        for (int q = 0; q < 4; q++) {
            float4 v = cp[q];
            h0 = fmaf(v.x, w[(4 * q + 0) * 3 + 0], h0);
            h1 = fmaf(v.x, w[(4 * q + 0) * 3 + 1], h1);
            h2 = fmaf(v.x, w[(4 * q + 0) * 3 + 2], h2);
            h0 = fmaf(v.y, w[(4 * q + 1) * 3 + 0], h0);
            h1 = fmaf(v.y, w[(4 * q + 1) * 3 + 1], h1);
            h2 = fmaf(v.y, w[(4 * q + 1) * 3 + 2], h2);
            h0 = fmaf(v.z, w[(4 * q + 2) * 3 + 0], h0);
            h1 = fmaf(v.z, w[(4 * q + 2) * 3 + 1], h1);
            h2 = fmaf(v.z, w[(4 * q + 2) * 3 + 2], h2);
            h0 = fmaf(v.w, w[(4 * q + 3) * 3 + 0], h0);
            h1 = fmaf(v.w, w[(4 * q + 3) * 3 + 1], h1);
            h2 = fmaf(v.w, w[(4 * q + 3) * 3 + 2], h2);
        }

        const float k = 0.70710678118654752f;
        float g0 = 0.5f * h0 * (1.0f + erff(h0 * k));
        float g1 = 0.5f * h1 * (1.0f + erff(h1 * k));
        float g2 = 0.5f * h2 * (1.0f + erff(h2 * k));
        float acc = g0 * wf0;
        acc = fmaf(g1, wf1, acc);
        acc = fmaf(g2, wf2, acc);

        acc += __shfl_xor_sync(0xFFFFFFFFu, acc, 1);
        if (par == 0) s_out[warp * CPB + cl] = acc;
    }
    __syncthreads();

    // ---- transposed write: thread t owns cell c0+t, two float4 stores ----
    const int c = threadIdx.x;
    float4 o0, o1;
    o0.x = s_out[0 * CPB + c];
    o0.y = s_out[1 * CPB + c];
    o0.z = s_out[2 * CPB + c];
    o0.w = s_out[3 * CPB + c];
    o1.x = s_out[4 * CPB + c];
    o1.y = s_out[5 * CPB + c];
    o1.z = s_out[6 * CPB + c];
    o1.w = s_out[7 * CPB + c];

    float* op = out + (size_t)(c0 + c) * RR + (size_t)blockIdx.y * RPB;
    ((float4*)op)[0] = o0;
    ((float4*)op)[1] = o1;
}

extern "C" void kernel_launch(void* const* d_in, const int* in_sizes, int n_in,
                              void* d_out, int out_size)
{
    const float* emb = (const float*)d_in[0];   // [R, C, DIN] f32
    const void*  oi  = d_in[1];                 // [R] int32/int64
    const float* W1  = (const float*)d_in[2];   // [NREG, DIN, E]
    const float* b1  = (const float*)d_in[3];   // [NREG, E]
    const float* Wf  = (const float*)d_in[4];   // [NREG, E, 1]
    float* out = (float*)d_out;                 // [C, R]

    dim3 grid(CC / CPB, RR / RPB);              // (32, 128)
    e2e_kernel<<<grid, 256>>>(emb, oi, W1, b1, Wf, out);
}